// round 1
// baseline (speedup 1.0000x reference)
#include <cuda_runtime.h>
#include <cuda_bf16.h>
#include <cstdint>

// Problem dims (fixed by the dataset)
#define BN 512   // batches
#define KN 128   // points per batch
#define DN 512   // feature dim

// Scratch (static device allocations are allowed)
__device__ float  g_cost[(size_t)BN * KN * KN];   // 33.5 MB, cost = -x.y
__device__ int    g_perm[BN * KN];
__device__ double g_partial[BN];

// ---------------------------------------------------------------------------
// Kernel 1: per-batch cost matrix C[b][i][j] = -(X[b,i,:] . Y[b,j,:])
// Row/col additive constants (|x|^2, |y|^2) do not change the LAP optimum.
// Tiled fp32 GEMM: block = 256 thr (16x16), 8x8 micro-tile, KC=32.
// ---------------------------------------------------------------------------
__global__ __launch_bounds__(256) void cost_kernel(const float* __restrict__ X,
                                                   const float* __restrict__ Y) {
    int b = blockIdx.x;
    __shared__ float As[32][132];   // [k][m], pad 132 for alignment/banks
    __shared__ float Bs[32][132];
    const float* xb = X + (size_t)b * KN * DN;
    const float* yb = Y + (size_t)b * KN * DN;
    int tid = threadIdx.x;
    int tx = tid & 15, ty = tid >> 4;

    float acc[8][8];
#pragma unroll
    for (int i = 0; i < 8; i++)
#pragma unroll
        for (int j = 0; j < 8; j++) acc[i][j] = 0.f;

    for (int k0 = 0; k0 < DN; k0 += 32) {
#pragma unroll
        for (int q = 0; q < 4; q++) {
            int idx = tid + 256 * q;          // 0..1023
            int row = idx >> 3;               // 0..127
            int kq  = (idx & 7) * 4;          // 0,4,...,28
            float4 xv = *(const float4*)(xb + row * DN + k0 + kq);
            float4 yv = *(const float4*)(yb + row * DN + k0 + kq);
            As[kq + 0][row] = xv.x; As[kq + 1][row] = xv.y;
            As[kq + 2][row] = xv.z; As[kq + 3][row] = xv.w;
            Bs[kq + 0][row] = yv.x; Bs[kq + 1][row] = yv.y;
            Bs[kq + 2][row] = yv.z; Bs[kq + 3][row] = yv.w;
        }
        __syncthreads();
#pragma unroll
        for (int kk = 0; kk < 32; kk++) {
            float a_[8], b_[8];
            // vectorized smem reads (132-float rows are 16B aligned)
            float4 a0 = *(const float4*)&As[kk][ty * 8 + 0];
            float4 a1 = *(const float4*)&As[kk][ty * 8 + 4];
            float4 b0 = *(const float4*)&Bs[kk][tx * 8 + 0];
            float4 b1 = *(const float4*)&Bs[kk][tx * 8 + 4];
            a_[0]=a0.x; a_[1]=a0.y; a_[2]=a0.z; a_[3]=a0.w;
            a_[4]=a1.x; a_[5]=a1.y; a_[6]=a1.z; a_[7]=a1.w;
            b_[0]=b0.x; b_[1]=b0.y; b_[2]=b0.z; b_[3]=b0.w;
            b_[4]=b1.x; b_[5]=b1.y; b_[6]=b1.z; b_[7]=b1.w;
#pragma unroll
            for (int i = 0; i < 8; i++)
#pragma unroll
                for (int j = 0; j < 8; j++) acc[i][j] += a_[i] * b_[j];
        }
        __syncthreads();
    }
    float* cb = g_cost + (size_t)b * KN * KN;
#pragma unroll
    for (int i = 0; i < 8; i++)
#pragma unroll
        for (int j = 0; j < 8; j++)
            cb[(ty * 8 + i) * KN + tx * 8 + j] = -acc[i][j];
}

// ---------------------------------------------------------------------------
// Kernel 2: Jonker-Volgenant LAP, one warp per batch.
// 1-based cols (col 0 virtual), each lane owns 4 real columns.
// Cost tile (64 KB) in dynamic shared memory.
// ---------------------------------------------------------------------------
__device__ __forceinline__ unsigned ordkey(float f) {
    unsigned u = __float_as_uint(f);
    return (u & 0x80000000u) ? ~u : (u | 0x80000000u);
}
__device__ __forceinline__ float unordkey(unsigned k) {
    unsigned u = (k & 0x80000000u) ? (k & 0x7fffffffu) : ~k;
    return __uint_as_float(u);
}

__global__ __launch_bounds__(32) void hungarian_kernel() {
    extern __shared__ float a_s[];         // 128*128 floats = 64 KB
    __shared__ float u_s[KN + 1];
    __shared__ int   p_s[KN + 1];
    __shared__ int   way_s[KN + 1];

    const int b = blockIdx.x;
    const int lane = threadIdx.x;
    const float INF = 1e30f;

    // load cost tile
    {
        const float4* src = (const float4*)(g_cost + (size_t)b * KN * KN);
        float4* dst = (float4*)a_s;
        for (int t = lane; t < KN * KN / 4; t += 32) dst[t] = src[t];
    }
    for (int t = lane; t <= KN; t += 32) { u_s[t] = 0.f; p_s[t] = 0; }
    float v_r[4] = {0.f, 0.f, 0.f, 0.f};
    __syncwarp();

    for (int i = 1; i <= KN; i++) {
        if (lane == 0) p_s[0] = i;
        float minv_r[4] = {INF, INF, INF, INF};
        bool  used_r[4] = {false, false, false, false};
        int j0 = 0;
        __syncwarp();

        while (true) {
            // mark used[j0]
            if (j0 != 0) {
                int jz = j0 - 1;
                if ((jz & 31) == lane) used_r[jz >> 5] = true;
            }
            int   i0   = p_s[j0];
            float u_i0 = u_s[i0];
            const float* arow = a_s + (i0 - 1) * KN;

            unsigned long long best = ~0ull;
#pragma unroll
            for (int c = 0; c < 4; c++) {
                int j = 1 + lane + 32 * c;
                if (!used_r[c]) {
                    float cur = arow[j - 1] - u_i0 - v_r[c];
                    if (cur < minv_r[c]) { minv_r[c] = cur; way_s[j] = j0; }
                    unsigned long long pk =
                        ((unsigned long long)ordkey(minv_r[c]) << 32) | (unsigned)j;
                    if (pk < best) best = pk;
                }
            }
#pragma unroll
            for (int s = 16; s; s >>= 1) {
                unsigned long long o = __shfl_xor_sync(0xffffffffu, best, s);
                if (o < best) best = o;
            }
            int   j1    = (int)(best & 0xffffffffu);
            float delta = unordkey((unsigned)(best >> 32));

            // potential updates: used cols (incl. virtual col 0)
            if (lane == 0) u_s[p_s[0]] += delta;
#pragma unroll
            for (int c = 0; c < 4; c++) {
                int j = 1 + lane + 32 * c;
                if (used_r[c]) { u_s[p_s[j]] += delta; v_r[c] -= delta; }
                else            minv_r[c] -= delta;
            }
            j0 = j1;
            __syncwarp();
            if (p_s[j0] == 0) break;
        }

        // augment along alternating path (lane 0, path is short)
        if (lane == 0) {
            int jj = j0;
            while (jj != 0) {
                int jn = way_s[jj];
                p_s[jj] = p_s[jn];
                jj = jn;
            }
        }
        __syncwarp();
    }

    // emit row->col permutation: perm[p[j]-1] = j-1
#pragma unroll
    for (int c = 0; c < 4; c++) {
        int j = 1 + lane + 32 * c;
        g_perm[b * KN + p_s[j] - 1] = j - 1;
    }
}

// ---------------------------------------------------------------------------
// Kernel 3: per-batch sum of (x - y[perm])^2, deterministic reduction
// ---------------------------------------------------------------------------
__global__ __launch_bounds__(256) void mse_kernel(const float* __restrict__ X,
                                                  const float* __restrict__ Y) {
    int b = blockIdx.x, tid = threadIdx.x;
    __shared__ int sperm[KN];
    if (tid < KN) sperm[tid] = g_perm[b * KN + tid];
    __syncthreads();

    const float4* xb = (const float4*)(X + (size_t)b * KN * DN);
    const float4* yb = (const float4*)(Y + (size_t)b * KN * DN);
    const int F4_PER_ROW = DN / 4;   // 128
    float acc = 0.f;
    for (int idx = tid; idx < KN * F4_PER_ROW; idx += 256) {
        int row = idx >> 7, col = idx & (F4_PER_ROW - 1);
        float4 xv = xb[row * F4_PER_ROW + col];
        float4 yv = yb[sperm[row] * F4_PER_ROW + col];
        float d0 = xv.x - yv.x, d1 = xv.y - yv.y;
        float d2 = xv.z - yv.z, d3 = xv.w - yv.w;
        acc += d0 * d0 + d1 * d1 + d2 * d2 + d3 * d3;
    }
    __shared__ double sred[256];
    sred[tid] = (double)acc;
    __syncthreads();
    for (int s = 128; s; s >>= 1) {
        if (tid < s) sred[tid] += sred[tid + s];
        __syncthreads();
    }
    if (tid == 0) g_partial[b] = sred[0];
}

__global__ __launch_bounds__(512) void finalize_kernel(float* __restrict__ out) {
    __shared__ double s[BN];
    int t = threadIdx.x;
    s[t] = g_partial[t];
    __syncthreads();
    for (int st = 256; st; st >>= 1) {
        if (t < st) s[t] += s[t + st];
        __syncthreads();
    }
    if (t == 0) out[0] = (float)(s[0] / ((double)BN * KN * DN));
}

// ---------------------------------------------------------------------------
extern "C" void kernel_launch(void* const* d_in, const int* in_sizes, int n_in,
                              void* d_out, int out_size) {
    const float* X = (const float*)d_in[0];   // input
    const float* Y = (const float*)d_in[1];   // target
    float* out = (float*)d_out;

    cudaFuncSetAttribute((const void*)hungarian_kernel,
                         cudaFuncAttributeMaxDynamicSharedMemorySize, 65536);

    cost_kernel<<<BN, 256>>>(X, Y);
    hungarian_kernel<<<BN, 32, 65536>>>();
    mse_kernel<<<BN, 256>>>(X, Y);
    finalize_kernel<<<1, 512>>>(out);
}

// round 2
// speedup vs baseline: 1.4939x; 1.4939x over previous
#include <cuda_runtime.h>
#include <cuda_fp16.h>
#include <cuda_bf16.h>
#include <cstdint>

#define BN 512   // batches
#define KN 128   // points per batch
#define DN 512   // feature dim

// Scratch (static device allocations allowed)
__device__ __half  g_cost[(size_t)BN * KN * KN];   // 16.8 MB, cost = -x.y (fp16)
__device__ int     g_perm[BN * KN];
__device__ double  g_partial[BN];

// ---------------------------------------------------------------------------
// Kernel 1: per-batch cost C[b][i][j] = -(X[b,i,:] . Y[b,j,:]), stored fp16.
// Row/col additive constants (|x|^2, |y|^2) don't change the LAP optimum, and
// the cost only drives the assignment (MSE recomputed in fp32 later), so fp16
// storage is safe.
// Grid: 1024 CTAs = 512 batches x 2 M-tiles (64 rows each). Block 128 thr,
// 8x8 micro-tile, KC=32.
// ---------------------------------------------------------------------------
__global__ __launch_bounds__(128) void cost_kernel(const float* __restrict__ X,
                                                   const float* __restrict__ Y) {
    int b    = blockIdx.x >> 1;
    int mhalf = blockIdx.x & 1;          // which 64-row slab of X
    __shared__ float As[32][68];         // [k][m] 64 rows + pad
    __shared__ float Bs[32][132];        // [k][n] 128 cols + pad
    const float* xb = X + (size_t)b * KN * DN + (size_t)mhalf * 64 * DN;
    const float* yb = Y + (size_t)b * KN * DN;
    int tid = threadIdx.x;
    int tx = tid & 15, ty = tid >> 4;    // tx->N(8 cols), ty->M(8 rows)

    float acc[8][8];
#pragma unroll
    for (int i = 0; i < 8; i++)
#pragma unroll
        for (int j = 0; j < 8; j++) acc[i][j] = 0.f;

    for (int k0 = 0; k0 < DN; k0 += 32) {
        // load As: 64x32 = 512 float4, 4 per thread
#pragma unroll
        for (int q = 0; q < 4; q++) {
            int idx = tid + 128 * q;          // 0..511
            int row = idx >> 3;               // 0..63
            int kq  = (idx & 7) * 4;
            float4 xv = *(const float4*)(xb + row * DN + k0 + kq);
            As[kq + 0][row] = xv.x; As[kq + 1][row] = xv.y;
            As[kq + 2][row] = xv.z; As[kq + 3][row] = xv.w;
        }
        // load Bs: 128x32 = 1024 float4, 8 per thread
#pragma unroll
        for (int q = 0; q < 8; q++) {
            int idx = tid + 128 * q;          // 0..1023
            int row = idx >> 3;               // 0..127
            int kq  = (idx & 7) * 4;
            float4 yv = *(const float4*)(yb + row * DN + k0 + kq);
            Bs[kq + 0][row] = yv.x; Bs[kq + 1][row] = yv.y;
            Bs[kq + 2][row] = yv.z; Bs[kq + 3][row] = yv.w;
        }
        __syncthreads();
#pragma unroll
        for (int kk = 0; kk < 32; kk++) {
            float a_[8], b_[8];
            float4 a0 = *(const float4*)&As[kk][ty * 8 + 0];
            float4 a1 = *(const float4*)&As[kk][ty * 8 + 4];
            float4 b0 = *(const float4*)&Bs[kk][tx * 8 + 0];
            float4 b1 = *(const float4*)&Bs[kk][tx * 8 + 4];
            a_[0]=a0.x; a_[1]=a0.y; a_[2]=a0.z; a_[3]=a0.w;
            a_[4]=a1.x; a_[5]=a1.y; a_[6]=a1.z; a_[7]=a1.w;
            b_[0]=b0.x; b_[1]=b0.y; b_[2]=b0.z; b_[3]=b0.w;
            b_[4]=b1.x; b_[5]=b1.y; b_[6]=b1.z; b_[7]=b1.w;
#pragma unroll
            for (int i = 0; i < 8; i++)
#pragma unroll
                for (int j = 0; j < 8; j++) acc[i][j] += a_[i] * b_[j];
        }
        __syncthreads();
    }
    __half* cb = g_cost + (size_t)b * KN * KN + (size_t)mhalf * 64 * KN;
#pragma unroll
    for (int i = 0; i < 8; i++) {
        __half2* dst = (__half2*)(cb + (ty * 8 + i) * KN + tx * 8);
#pragma unroll
        for (int j = 0; j < 4; j++)
            dst[j] = __floats2half2_rn(-acc[i][2 * j], -acc[i][2 * j + 1]);
    }
}

// ---------------------------------------------------------------------------
// Kernel 2: Jonker-Volgenant LAP, one warp per batch, fp16 cost tile (32 KB).
// 1-based cols (col 0 virtual), each lane owns 4 real columns.
// ---------------------------------------------------------------------------
__global__ __launch_bounds__(32) void hungarian_kernel() {
    extern __shared__ __half a_s[];        // 128*128 halfs = 32 KB
    __shared__ float u_s[KN + 1];
    __shared__ int   p_s[KN + 1];
    __shared__ int   way_s[KN + 1];

    const int b = blockIdx.x;
    const int lane = threadIdx.x;
    const float INF = 1e30f;

    // load cost tile: 32 KB as uint4
    {
        const uint4* src = (const uint4*)(g_cost + (size_t)b * KN * KN);
        uint4* dst = (uint4*)a_s;
#pragma unroll
        for (int q = 0; q < 64; q++) dst[lane + 32 * q] = src[lane + 32 * q];
    }
    for (int t = lane; t <= KN; t += 32) { u_s[t] = 0.f; p_s[t] = 0; }
    float v_r[4] = {0.f, 0.f, 0.f, 0.f};
    __syncwarp();

    for (int i = 1; i <= KN; i++) {
        if (lane == 0) p_s[0] = i;
        float minv_r[4] = {INF, INF, INF, INF};
        bool  used_r[4] = {false, false, false, false};
        int j0 = 0;
        __syncwarp();

        while (true) {
            if (j0 != 0) {
                int jz = j0 - 1;
                if ((jz & 31) == lane) used_r[jz >> 5] = true;
            }
            int   i0   = p_s[j0];
            float u_i0 = u_s[i0];
            const __half* arow = a_s + (i0 - 1) * KN;

            // relax + local argmin over this lane's free columns
            float bestv = INF;
            int   bestj = 0;
#pragma unroll
            for (int c = 0; c < 4; c++) {
                int j = 1 + lane + 32 * c;
                if (!used_r[c]) {
                    float cur = __half2float(arow[j - 1]) - u_i0 - v_r[c];
                    if (cur < minv_r[c]) { minv_r[c] = cur; way_s[j] = j0; }
                    if (minv_r[c] < bestv) { bestv = minv_r[c]; bestj = j; }
                }
            }
            // warp argmin: float min butterfly, then pick a winning lane
            float m = bestv;
#pragma unroll
            for (int s = 16; s; s >>= 1)
                m = fminf(m, __shfl_xor_sync(0xffffffffu, m, s));
            unsigned msk = __ballot_sync(0xffffffffu, bestv == m);
            int src = __ffs(msk) - 1;
            int j1 = __shfl_sync(0xffffffffu, bestj, src);
            float delta = m;

            // potential updates
            if (lane == 0) u_s[p_s[0]] += delta;
#pragma unroll
            for (int c = 0; c < 4; c++) {
                int j = 1 + lane + 32 * c;
                if (used_r[c]) { u_s[p_s[j]] += delta; v_r[c] -= delta; }
                else            minv_r[c] -= delta;
            }
            j0 = j1;
            __syncwarp();
            if (p_s[j0] == 0) break;
        }

        // augment along alternating path (lane 0)
        if (lane == 0) {
            int jj = j0;
            while (jj != 0) {
                int jn = way_s[jj];
                p_s[jj] = p_s[jn];
                jj = jn;
            }
        }
        __syncwarp();
    }

#pragma unroll
    for (int c = 0; c < 4; c++) {
        int j = 1 + lane + 32 * c;
        g_perm[b * KN + p_s[j] - 1] = j - 1;
    }
}

// ---------------------------------------------------------------------------
// Kernel 3: per-batch sum of (x - y[perm])^2 in fp32, deterministic reduction
// ---------------------------------------------------------------------------
__global__ __launch_bounds__(256) void mse_kernel(const float* __restrict__ X,
                                                  const float* __restrict__ Y) {
    int b = blockIdx.x, tid = threadIdx.x;
    __shared__ int sperm[KN];
    if (tid < KN) sperm[tid] = g_perm[b * KN + tid];
    __syncthreads();

    const float4* xb = (const float4*)(X + (size_t)b * KN * DN);
    const float4* yb = (const float4*)(Y + (size_t)b * KN * DN);
    const int F4_PER_ROW = DN / 4;   // 128
    float acc = 0.f;
    for (int idx = tid; idx < KN * F4_PER_ROW; idx += 256) {
        int row = idx >> 7, col = idx & (F4_PER_ROW - 1);
        float4 xv = xb[row * F4_PER_ROW + col];
        float4 yv = yb[sperm[row] * F4_PER_ROW + col];
        float d0 = xv.x - yv.x, d1 = xv.y - yv.y;
        float d2 = xv.z - yv.z, d3 = xv.w - yv.w;
        acc += d0 * d0 + d1 * d1 + d2 * d2 + d3 * d3;
    }
    __shared__ double sred[256];
    sred[tid] = (double)acc;
    __syncthreads();
    for (int s = 128; s; s >>= 1) {
        if (tid < s) sred[tid] += sred[tid + s];
        __syncthreads();
    }
    if (tid == 0) g_partial[b] = sred[0];
}

__global__ __launch_bounds__(512) void finalize_kernel(float* __restrict__ out) {
    __shared__ double s[BN];
    int t = threadIdx.x;
    s[t] = g_partial[t];
    __syncthreads();
    for (int st = 256; st; st >>= 1) {
        if (t < st) s[t] += s[t + st];
        __syncthreads();
    }
    if (t == 0) out[0] = (float)(s[0] / ((double)BN * KN * DN));
}

// ---------------------------------------------------------------------------
extern "C" void kernel_launch(void* const* d_in, const int* in_sizes, int n_in,
                              void* d_out, int out_size) {
    const float* X = (const float*)d_in[0];   // input
    const float* Y = (const float*)d_in[1];   // target
    float* out = (float*)d_out;

    cost_kernel<<<BN * 2, 128>>>(X, Y);
    hungarian_kernel<<<BN, 32, KN * KN * (int)sizeof(__half)>>>();
    mse_kernel<<<BN, 256>>>(X, Y);
    finalize_kernel<<<1, 512>>>(out);
}

// round 4
// speedup vs baseline: 2.7049x; 1.8106x over previous
#include <cuda_runtime.h>
#include <cuda_fp16.h>
#include <cuda_bf16.h>
#include <cstdint>

#define BN 512   // batches
#define KN 128   // points per batch
#define DN 512   // feature dim

// Scratch (static device allocations allowed)
__device__ __half  g_cost[(size_t)BN * KN * KN];   // 16.8 MB, cost = -x.y (fp16)
__device__ int     g_perm[BN * KN];
__device__ double  g_partial[BN];

// ---------------------------------------------------------------------------
// helpers
// ---------------------------------------------------------------------------
__device__ __forceinline__ uint32_t smem_u32(const void* p) {
    return (uint32_t)__cvta_generic_to_shared(p);
}
__device__ __forceinline__ void ldsm_x4(uint32_t& r0, uint32_t& r1,
                                        uint32_t& r2, uint32_t& r3, uint32_t addr) {
    asm volatile("ldmatrix.sync.aligned.m8n8.x4.shared.b16 {%0,%1,%2,%3}, [%4];"
                 : "=r"(r0), "=r"(r1), "=r"(r2), "=r"(r3) : "r"(addr));
}
__device__ __forceinline__ void mma_bf16(float& c0, float& c1, float& c2, float& c3,
                                         uint32_t a0, uint32_t a1, uint32_t a2, uint32_t a3,
                                         uint32_t b0, uint32_t b1) {
    asm volatile("mma.sync.aligned.m16n8k16.row.col.f32.bf16.bf16.f32 "
                 "{%0,%1,%2,%3}, {%4,%5,%6,%7}, {%8,%9}, {%0,%1,%2,%3};"
                 : "+f"(c0), "+f"(c1), "+f"(c2), "+f"(c3)
                 : "r"(a0), "r"(a1), "r"(a2), "r"(a3), "r"(b0), "r"(b1));
}
__device__ __forceinline__ unsigned redux_min_u32(unsigned v) {
    unsigned r;
    asm("redux.sync.min.u32 %0, %1, 0xffffffff;" : "=r"(r) : "r"(v));
    return r;
}
__device__ __forceinline__ unsigned ordkey(float f) {
    unsigned u = __float_as_uint(f);
    return (u & 0x80000000u) ? ~u : (u | 0x80000000u);
}
__device__ __forceinline__ float unordkey(unsigned k) {
    unsigned u = (k & 0x80000000u) ? (k & 0x7fffffffu) : ~k;
    return __uint_as_float(u);
}

// ---------------------------------------------------------------------------
// Kernel 1: C[b][i][j] = -(X[b,i,:] . Y[b,j,:]), bf16 MMA, fp16 output.
// One CTA per batch. 256 thr = 8 warps in a 2(M) x 4(N) grid; warp tile 64x32.
// Smem: X/Y tiles 128 x 64 bf16 each, 16B-chunk XOR swizzle, ldmatrix feeds.
// ---------------------------------------------------------------------------
__device__ __forceinline__ int chunk_off(int row, int c) {   // in 16B units
    return row * 8 + (c ^ (row & 7));
}

__global__ __launch_bounds__(256) void cost_kernel(const float* __restrict__ X,
                                                   const float* __restrict__ Y) {
    __shared__ uint4 Xs[1024];   // 16 KB: 128 rows x 8 chunks
    __shared__ uint4 Ys[1024];   // 16 KB

    const int b   = blockIdx.x;
    const int tid = threadIdx.x;
    const int w    = tid >> 5;
    const int lane = tid & 31;
    const int wm = w >> 2;       // 0..1  -> m base = wm*64
    const int wn = w & 3;        // 0..3  -> n base = wn*32

    const float* xb = X + (size_t)b * KN * DN;
    const float* yb = Y + (size_t)b * KN * DN;

    float acc[4][4][4];
#pragma unroll
    for (int mt = 0; mt < 4; mt++)
#pragma unroll
        for (int nt = 0; nt < 4; nt++)
#pragma unroll
            for (int q = 0; q < 4; q++) acc[mt][nt][q] = 0.f;

    const uint32_t xs_base = smem_u32(Xs);
    const uint32_t ys_base = smem_u32(Ys);

    for (int kb = 0; kb < 8; kb++) {     // K blocks of 64
        // load + convert: 1024 chunks per tile, 4 per thread per tile
#pragma unroll
        for (int qi = 0; qi < 4; qi++) {
            int q   = tid + 256 * qi;    // 0..1023
            int row = q >> 3;
            int c   = q & 7;
            const float* sx = xb + row * DN + kb * 64 + c * 8;
            const float* sy = yb + row * DN + kb * 64 + c * 8;
            float4 f0 = *(const float4*)sx;
            float4 f1 = *(const float4*)(sx + 4);
            uint4 pk;
            { __nv_bfloat162 t0 = __floats2bfloat162_rn(f0.x, f0.y); pk.x = *(uint32_t*)&t0; }
            { __nv_bfloat162 t1 = __floats2bfloat162_rn(f0.z, f0.w); pk.y = *(uint32_t*)&t1; }
            { __nv_bfloat162 t2 = __floats2bfloat162_rn(f1.x, f1.y); pk.z = *(uint32_t*)&t2; }
            { __nv_bfloat162 t3 = __floats2bfloat162_rn(f1.z, f1.w); pk.w = *(uint32_t*)&t3; }
            Xs[chunk_off(row, c)] = pk;
            float4 g0 = *(const float4*)sy;
            float4 g1 = *(const float4*)(sy + 4);
            { __nv_bfloat162 t0 = __floats2bfloat162_rn(g0.x, g0.y); pk.x = *(uint32_t*)&t0; }
            { __nv_bfloat162 t1 = __floats2bfloat162_rn(g0.z, g0.w); pk.y = *(uint32_t*)&t1; }
            { __nv_bfloat162 t2 = __floats2bfloat162_rn(g1.x, g1.y); pk.z = *(uint32_t*)&t2; }
            { __nv_bfloat162 t3 = __floats2bfloat162_rn(g1.z, g1.w); pk.w = *(uint32_t*)&t3; }
            Ys[chunk_off(row, c)] = pk;
        }
        __syncthreads();

#pragma unroll
        for (int ks = 0; ks < 4; ks++) {      // k16 steps within block
            const int sub = lane >> 3;
            const int r   = lane & 7;
            // A fragments: 4 m-tiles
            uint32_t A[4][4];
#pragma unroll
            for (int mt = 0; mt < 4; mt++) {
                int rowA = wm * 64 + mt * 16 + (sub & 1) * 8 + r;
                int kch  = ks * 2 + (sub >> 1);
                uint32_t ad = xs_base + (uint32_t)(chunk_off(rowA, kch) << 4);
                ldsm_x4(A[mt][0], A[mt][1], A[mt][2], A[mt][3], ad);
            }
            // B fragments: 2 groups x (2 n-tiles each)
            uint32_t Bf[2][4];
#pragma unroll
            for (int g2 = 0; g2 < 2; g2++) {
                int rowB = wn * 32 + g2 * 16 + (sub >> 1) * 8 + r;
                int kch  = ks * 2 + (sub & 1);
                uint32_t ad = ys_base + (uint32_t)(chunk_off(rowB, kch) << 4);
                ldsm_x4(Bf[g2][0], Bf[g2][1], Bf[g2][2], Bf[g2][3], ad);
            }
#pragma unroll
            for (int mt = 0; mt < 4; mt++)
#pragma unroll
                for (int nt = 0; nt < 4; nt++) {
                    int g2 = nt >> 1, h = nt & 1;
                    mma_bf16(acc[mt][nt][0], acc[mt][nt][1], acc[mt][nt][2], acc[mt][nt][3],
                             A[mt][0], A[mt][1], A[mt][2], A[mt][3],
                             Bf[g2][h * 2 + 0], Bf[g2][h * 2 + 1]);
                }
        }
        __syncthreads();
    }

    // epilogue: negate, write fp16
    __half* cb = g_cost + (size_t)b * KN * KN;
    const int g = lane >> 2, t = lane & 3;
#pragma unroll
    for (int mt = 0; mt < 4; mt++)
#pragma unroll
        for (int nt = 0; nt < 4; nt++) {
            int row0 = wm * 64 + mt * 16 + g;
            int col  = wn * 32 + nt * 8 + 2 * t;
            *(__half2*)(cb + row0 * KN + col) =
                __floats2half2_rn(-acc[mt][nt][0], -acc[mt][nt][1]);
            *(__half2*)(cb + (row0 + 8) * KN + col) =
                __floats2half2_rn(-acc[mt][nt][2], -acc[mt][nt][3]);
        }
}

// ---------------------------------------------------------------------------
// Kernel 2: Jonker-Volgenant LAP (deferred potential updates), one warp/batch.
// Lane owns 4 consecutive columns (4*lane .. 4*lane+3, 0-based).
// Inner Dijkstra: dist relaxed against cumulative delta D; u/v applied once
// per augmentation. Warp argmin via redux.sync.min.u32 on ordered-float keys.
// ---------------------------------------------------------------------------
__global__ __launch_bounds__(32) void hungarian_kernel() {
    extern __shared__ __half a_s[];        // 128*128 halfs = 32 KB
    __shared__ float u_s[KN + 1];
    __shared__ int   p_s[KN + 1];          // p[j] = row matched to col j (1-based)

    const int b = blockIdx.x;
    const int lane = threadIdx.x;
    const float INF = 1e30f;

    {   // load cost tile (2048 uint4)
        const uint4* src = (const uint4*)(g_cost + (size_t)b * KN * KN);
        uint4* dst = (uint4*)a_s;
#pragma unroll
        for (int q = 0; q < 64; q++) dst[lane + 32 * q] = src[lane + 32 * q];
    }
    for (int t = lane; t <= KN; t += 32) { u_s[t] = 0.f; p_s[t] = 0; }
    float v_r[4] = {0.f, 0.f, 0.f, 0.f};
    __syncwarp();

    for (int i = 1; i <= KN; i++) {
        if (lane == 0) p_s[0] = i;
        float dist[4] = {INF, INF, INF, INF};
        int   way[4]  = {0, 0, 0, 0};
        bool  used[4] = {false, false, false, false};
        int   j0 = 0;
        float D  = 0.f;
        __syncwarp();

        while (true) {
            const int   i0 = p_s[j0];
            const float s  = D - u_s[i0];
            // 4 consecutive halfs, one 8B load, conflict-free
            uint2 rw = *(const uint2*)(a_s + (i0 - 1) * KN + 4 * lane);
            __half2 h01 = *(__half2*)&rw.x;
            __half2 h23 = *(__half2*)&rw.y;
            float av[4] = { __low2float(h01), __high2float(h01),
                            __low2float(h23), __high2float(h23) };

            float bestv = INF;
            int   bestc = 0;
#pragma unroll
            for (int c = 0; c < 4; c++) {
                if (!used[c]) {
                    float cur = av[c] - v_r[c] + s;
                    if (cur < dist[c]) { dist[c] = cur; way[c] = j0; }
                    if (dist[c] < bestv) { bestv = dist[c]; bestc = c; }
                }
            }
            unsigned key = ordkey(bestv);
            unsigned mk  = redux_min_u32(key);
            unsigned msk = __ballot_sync(0xffffffffu, key == mk);
            int srcl = __ffs(msk) - 1;
            int j1 = __shfl_sync(0xffffffffu, 4 * lane + bestc + 1, srcl);
            D = unordkey(mk);

            j0 = j1;
            bool done = (p_s[j0] == 0);
            if (!done && lane == srcl) used[bestc] = true;
            if (done) break;
        }

        // apply deferred potential updates (before augment; p_s still old)
#pragma unroll
        for (int c = 0; c < 4; c++) {
            if (used[c]) {
                float dd = D - dist[c];
                v_r[c] -= dd;
                int j = 4 * lane + c + 1;
                u_s[p_s[j]] += dd;         // matched rows distinct -> no race
            }
        }
        if (lane == 0) u_s[i] += D;
        __syncwarp();

        // augment along alternating path; way lives in registers, shfl to walk
        int jj = j0;
        while (jj != 0) {
            int o = jj - 1;
            int c = o & 3;
            int myway = (c == 0) ? way[0] : (c == 1) ? way[1] : (c == 2) ? way[2] : way[3];
            int jn = __shfl_sync(0xffffffffu, myway, o >> 2);
            if (lane == 0) p_s[jj] = p_s[jn];
            __syncwarp();
            jj = jn;
        }
        __syncwarp();
    }

    // emit row->col permutation: perm[p[j]-1] = j-1
#pragma unroll
    for (int c = 0; c < 4; c++) {
        int j = 4 * lane + c + 1;
        g_perm[b * KN + p_s[j] - 1] = j - 1;
    }
}

// ---------------------------------------------------------------------------
// Kernel 3: per-batch sum of (x - y[perm])^2 in fp32, deterministic reduction
// ---------------------------------------------------------------------------
__global__ __launch_bounds__(256) void mse_kernel(const float* __restrict__ X,
                                                  const float* __restrict__ Y) {
    int b = blockIdx.x, tid = threadIdx.x;
    __shared__ int sperm[KN];
    if (tid < KN) sperm[tid] = g_perm[b * KN + tid];
    __syncthreads();

    const float4* xb = (const float4*)(X + (size_t)b * KN * DN);
    const float4* yb = (const float4*)(Y + (size_t)b * KN * DN);
    const int F4_PER_ROW = DN / 4;   // 128
    float acc = 0.f;
    for (int idx = tid; idx < KN * F4_PER_ROW; idx += 256) {
        int row = idx >> 7, col = idx & (F4_PER_ROW - 1);
        float4 xv = xb[row * F4_PER_ROW + col];
        float4 yv = yb[sperm[row] * F4_PER_ROW + col];
        float d0 = xv.x - yv.x, d1 = xv.y - yv.y;
        float d2 = xv.z - yv.z, d3 = xv.w - yv.w;
        acc += d0 * d0 + d1 * d1 + d2 * d2 + d3 * d3;
    }
    __shared__ double sred[256];
    sred[tid] = (double)acc;
    __syncthreads();
    for (int s = 128; s; s >>= 1) {
        if (tid < s) sred[tid] += sred[tid + s];
        __syncthreads();
    }
    if (tid == 0) g_partial[b] = sred[0];
}

__global__ __launch_bounds__(512) void finalize_kernel(float* __restrict__ out) {
    __shared__ double s[BN];
    int t = threadIdx.x;
    s[t] = g_partial[t];
    __syncthreads();
    for (int st = 256; st; st >>= 1) {
        if (t < st) s[t] += s[t + st];
        __syncthreads();
    }
    if (t == 0) out[0] = (float)(s[0] / ((double)BN * KN * DN));
}

// ---------------------------------------------------------------------------
extern "C" void kernel_launch(void* const* d_in, const int* in_sizes, int n_in,
                              void* d_out, int out_size) {
    const float* X = (const float*)d_in[0];   // input
    const float* Y = (const float*)d_in[1];   // target
    float* out = (float*)d_out;

    cost_kernel<<<BN, 256>>>(X, Y);
    hungarian_kernel<<<BN, 32, KN * KN * (int)sizeof(__half)>>>();
    mse_kernel<<<BN, 256>>>(X, Y);
    finalize_kernel<<<1, 512>>>(out);
}

// round 5
// speedup vs baseline: 3.1913x; 1.1798x over previous
#include <cuda_runtime.h>
#include <cuda_fp16.h>
#include <cuda_bf16.h>
#include <cstdint>

#define BN 512   // batches
#define KN 128   // points per batch
#define DN 512   // feature dim

// Scratch (static device allocations allowed)
__device__ __half  g_cost[(size_t)BN * KN * KN];   // 16.8 MB, cost = -x.y (fp16)
__device__ int     g_perm[BN * KN];
__device__ double  g_partial[BN];

// ---------------------------------------------------------------------------
// helpers
// ---------------------------------------------------------------------------
__device__ __forceinline__ uint32_t smem_u32(const void* p) {
    return (uint32_t)__cvta_generic_to_shared(p);
}
__device__ __forceinline__ void ldsm_x4(uint32_t& r0, uint32_t& r1,
                                        uint32_t& r2, uint32_t& r3, uint32_t addr) {
    asm volatile("ldmatrix.sync.aligned.m8n8.x4.shared.b16 {%0,%1,%2,%3}, [%4];"
                 : "=r"(r0), "=r"(r1), "=r"(r2), "=r"(r3) : "r"(addr));
}
__device__ __forceinline__ void mma_bf16(float& c0, float& c1, float& c2, float& c3,
                                         uint32_t a0, uint32_t a1, uint32_t a2, uint32_t a3,
                                         uint32_t b0, uint32_t b1) {
    asm volatile("mma.sync.aligned.m16n8k16.row.col.f32.bf16.bf16.f32 "
                 "{%0,%1,%2,%3}, {%4,%5,%6,%7}, {%8,%9}, {%0,%1,%2,%3};"
                 : "+f"(c0), "+f"(c1), "+f"(c2), "+f"(c3)
                 : "r"(a0), "r"(a1), "r"(a2), "r"(a3), "r"(b0), "r"(b1));
}
__device__ __forceinline__ unsigned redux_min_u32(unsigned v) {
    unsigned r;
    asm("redux.sync.min.u32 %0, %1, 0xffffffff;" : "=r"(r) : "r"(v));
    return r;
}
__device__ __forceinline__ unsigned ordkey(float f) {
    unsigned u = __float_as_uint(f);
    return (u & 0x80000000u) ? ~u : (u | 0x80000000u);
}
__device__ __forceinline__ float unordkey(unsigned k) {
    unsigned u = (k & 0x80000000u) ? (k & 0x7fffffffu) : ~k;
    return __uint_as_float(u);
}

// ---------------------------------------------------------------------------
// Kernel 1: C[b][i][j] = -(X[b,i,:] . Y[b,j,:]), bf16 MMA, fp16 output.
// One CTA per batch. 256 thr = 8 warps in a 2(M) x 4(N) grid; warp tile 64x32.
// ---------------------------------------------------------------------------
__device__ __forceinline__ int chunk_off(int row, int c) {   // in 16B units
    return row * 8 + (c ^ (row & 7));
}

__global__ __launch_bounds__(256) void cost_kernel(const float* __restrict__ X,
                                                   const float* __restrict__ Y) {
    __shared__ uint4 Xs[1024];   // 16 KB: 128 rows x 8 chunks
    __shared__ uint4 Ys[1024];   // 16 KB

    const int b   = blockIdx.x;
    const int tid = threadIdx.x;
    const int w    = tid >> 5;
    const int lane = tid & 31;
    const int wm = w >> 2;       // 0..1  -> m base = wm*64
    const int wn = w & 3;        // 0..3  -> n base = wn*32

    const float* xb = X + (size_t)b * KN * DN;
    const float* yb = Y + (size_t)b * KN * DN;

    float acc[4][4][4];
#pragma unroll
    for (int mt = 0; mt < 4; mt++)
#pragma unroll
        for (int nt = 0; nt < 4; nt++)
#pragma unroll
            for (int q = 0; q < 4; q++) acc[mt][nt][q] = 0.f;

    const uint32_t xs_base = smem_u32(Xs);
    const uint32_t ys_base = smem_u32(Ys);

    for (int kb = 0; kb < 8; kb++) {     // K blocks of 64
#pragma unroll
        for (int qi = 0; qi < 4; qi++) {
            int q   = tid + 256 * qi;    // 0..1023
            int row = q >> 3;
            int c   = q & 7;
            const float* sx = xb + row * DN + kb * 64 + c * 8;
            const float* sy = yb + row * DN + kb * 64 + c * 8;
            float4 f0 = *(const float4*)sx;
            float4 f1 = *(const float4*)(sx + 4);
            uint4 pk;
            { __nv_bfloat162 t0 = __floats2bfloat162_rn(f0.x, f0.y); pk.x = *(uint32_t*)&t0; }
            { __nv_bfloat162 t1 = __floats2bfloat162_rn(f0.z, f0.w); pk.y = *(uint32_t*)&t1; }
            { __nv_bfloat162 t2 = __floats2bfloat162_rn(f1.x, f1.y); pk.z = *(uint32_t*)&t2; }
            { __nv_bfloat162 t3 = __floats2bfloat162_rn(f1.z, f1.w); pk.w = *(uint32_t*)&t3; }
            Xs[chunk_off(row, c)] = pk;
            float4 g0 = *(const float4*)sy;
            float4 g1 = *(const float4*)(sy + 4);
            { __nv_bfloat162 t0 = __floats2bfloat162_rn(g0.x, g0.y); pk.x = *(uint32_t*)&t0; }
            { __nv_bfloat162 t1 = __floats2bfloat162_rn(g0.z, g0.w); pk.y = *(uint32_t*)&t1; }
            { __nv_bfloat162 t2 = __floats2bfloat162_rn(g1.x, g1.y); pk.z = *(uint32_t*)&t2; }
            { __nv_bfloat162 t3 = __floats2bfloat162_rn(g1.z, g1.w); pk.w = *(uint32_t*)&t3; }
            Ys[chunk_off(row, c)] = pk;
        }
        __syncthreads();

#pragma unroll
        for (int ks = 0; ks < 4; ks++) {      // k16 steps within block
            const int sub = lane >> 3;
            const int r   = lane & 7;
            uint32_t A[4][4];
#pragma unroll
            for (int mt = 0; mt < 4; mt++) {
                int rowA = wm * 64 + mt * 16 + (sub & 1) * 8 + r;
                int kch  = ks * 2 + (sub >> 1);
                uint32_t ad = xs_base + (uint32_t)(chunk_off(rowA, kch) << 4);
                ldsm_x4(A[mt][0], A[mt][1], A[mt][2], A[mt][3], ad);
            }
            uint32_t Bf[2][4];
#pragma unroll
            for (int g2 = 0; g2 < 2; g2++) {
                int rowB = wn * 32 + g2 * 16 + (sub >> 1) * 8 + r;
                int kch  = ks * 2 + (sub & 1);
                uint32_t ad = ys_base + (uint32_t)(chunk_off(rowB, kch) << 4);
                ldsm_x4(Bf[g2][0], Bf[g2][1], Bf[g2][2], Bf[g2][3], ad);
            }
#pragma unroll
            for (int mt = 0; mt < 4; mt++)
#pragma unroll
                for (int nt = 0; nt < 4; nt++) {
                    int g2 = nt >> 1, h = nt & 1;
                    mma_bf16(acc[mt][nt][0], acc[mt][nt][1], acc[mt][nt][2], acc[mt][nt][3],
                             A[mt][0], A[mt][1], A[mt][2], A[mt][3],
                             Bf[g2][h * 2 + 0], Bf[g2][h * 2 + 1]);
                }
        }
        __syncthreads();
    }

    __half* cb = g_cost + (size_t)b * KN * KN;
    const int g = lane >> 2, t = lane & 3;
#pragma unroll
    for (int mt = 0; mt < 4; mt++)
#pragma unroll
        for (int nt = 0; nt < 4; nt++) {
            int row0 = wm * 64 + mt * 16 + g;
            int col  = wn * 32 + nt * 8 + 2 * t;
            *(__half2*)(cb + row0 * KN + col) =
                __floats2half2_rn(-acc[mt][nt][0], -acc[mt][nt][1]);
            *(__half2*)(cb + (row0 + 8) * KN + col) =
                __floats2half2_rn(-acc[mt][nt][2], -acc[mt][nt][3]);
        }
}

// ---------------------------------------------------------------------------
// Kernel 2: Jonker-Volgenant LAP, one warp/batch, fp16 cost tile (32 KB).
// Lane owns 4 consecutive columns. Deferred dual updates.
// Per-column packed {matched_row, u[matched_row]} (int2) -> one LDS.64 on the
// critical path instead of three LDS.32. Warp argmin via one redux.sync.min
// on a key with the column index embedded in the low 7 bits.
// ---------------------------------------------------------------------------
__global__ __launch_bounds__(32) void hungarian_kernel() {
    extern __shared__ __half a_s[];        // 128*128 halfs = 32 KB
    __shared__ int2 pu_s[KN + 1];          // [col] = {row (1-based, 0=free), u_bits}

    const int b = blockIdx.x;
    const int lane = threadIdx.x;
    const float INF = 1e30f;

    {   // load cost tile (2048 uint4)
        const uint4* src = (const uint4*)(g_cost + (size_t)b * KN * KN);
        uint4* dst = (uint4*)a_s;
#pragma unroll
        for (int q = 0; q < 64; q++) dst[lane + 32 * q] = src[lane + 32 * q];
    }
    for (int t = lane; t <= KN; t += 32) pu_s[t] = make_int2(0, 0);
    float v_r[4] = {0.f, 0.f, 0.f, 0.f};
    __syncwarp();

    for (int i = 1; i <= KN; i++) {
        float dist[4] = {INF, INF, INF, INF};
        int   way[4]  = {0, 0, 0, 0};
        bool  used[4] = {false, false, false, false};
        int   i0 = i;          // fresh row starts the tree
        float u_i0 = 0.f;      // fresh rows have u == 0
        float D  = 0.f;
        int   prevj = 0;
        int   j0;

        for (;;) {
            const float s = D - u_i0;
            // this lane's 4 consecutive costs of row i0: one LDS.64
            uint2 rw = *(const uint2*)(a_s + (i0 - 1) * KN + 4 * lane);
            float2 f01 = __half22float2(*(const __half2*)&rw.x);
            float2 f23 = __half22float2(*(const __half2*)&rw.y);
            float av[4] = { f01.x, f01.y, f23.x, f23.y };

            unsigned bestkey = 0xffffffffu;
#pragma unroll
            for (int c = 0; c < 4; c++) {
                if (!used[c]) {
                    float cur = av[c] + (s - v_r[c]);
                    if (cur < dist[c]) { dist[c] = cur; way[c] = prevj; }
                    unsigned k = (ordkey(dist[c]) & ~127u) | (unsigned)(4 * lane + c);
                    bestkey = min(bestkey, k);
                }
            }
            unsigned mk = redux_min_u32(bestkey);
            D = unordkey(mk);                 // consistent across lanes
            int jg = mk & 127;                // winning column, 0-based
            int j1 = jg + 1;
            prevj = j1;

            int2 pu = pu_s[j1];               // {row, u} packed, one LDS.64
            bool done = (pu.x == 0);
            if (!done && (jg >> 2) == lane) used[jg & 3] = true;
            if (done) { j0 = j1; break; }
            i0 = pu.x;
            u_i0 = __int_as_float(pu.y);
        }

        // deferred dual updates (old matching; each matched row in exactly 1 col)
#pragma unroll
        for (int c = 0; c < 4; c++) {
            if (used[c]) {
                float dd = D - dist[c];
                v_r[c] -= dd;
                int j = 4 * lane + c + 1;
                pu_s[j].y = __float_as_int(__int_as_float(pu_s[j].y) + dd);
            }
        }
        if (lane == 0) pu_s[0] = make_int2(i, __float_as_int(D));  // row i enters with u=D
        __syncwarp();

        // augment: shift {row,u} pairs along alternating path
        int jj = j0;
        while (jj != 0) {
            int o = jj - 1;
            int c = o & 3;
            int sel = (c == 0) ? way[0] : (c == 1) ? way[1] : (c == 2) ? way[2] : way[3];
            int jn = __shfl_sync(0xffffffffu, sel, o >> 2);
            if (lane == 0) pu_s[jj] = pu_s[jn];
            __syncwarp();
            jj = jn;
        }
        __syncwarp();
    }

    // emit row->col permutation: perm[row-1] = col-1
#pragma unroll
    for (int c = 0; c < 4; c++) {
        int j = 4 * lane + c + 1;
        g_perm[b * KN + pu_s[j].x - 1] = j - 1;
    }
}

// ---------------------------------------------------------------------------
// Kernel 3: per-batch sum of (x - y[perm])^2 in fp32, deterministic reduction
// ---------------------------------------------------------------------------
__global__ __launch_bounds__(256) void mse_kernel(const float* __restrict__ X,
                                                  const float* __restrict__ Y) {
    int b = blockIdx.x, tid = threadIdx.x;
    __shared__ int sperm[KN];
    if (tid < KN) sperm[tid] = g_perm[b * KN + tid];
    __syncthreads();

    const float4* xb = (const float4*)(X + (size_t)b * KN * DN);
    const float4* yb = (const float4*)(Y + (size_t)b * KN * DN);
    const int F4_PER_ROW = DN / 4;   // 128
    float acc = 0.f;
    for (int idx = tid; idx < KN * F4_PER_ROW; idx += 256) {
        int row = idx >> 7, col = idx & (F4_PER_ROW - 1);
        float4 xv = xb[row * F4_PER_ROW + col];
        float4 yv = yb[sperm[row] * F4_PER_ROW + col];
        float d0 = xv.x - yv.x, d1 = xv.y - yv.y;
        float d2 = xv.z - yv.z, d3 = xv.w - yv.w;
        acc += d0 * d0 + d1 * d1 + d2 * d2 + d3 * d3;
    }
    __shared__ double sred[256];
    sred[tid] = (double)acc;
    __syncthreads();
    for (int s = 128; s; s >>= 1) {
        if (tid < s) sred[tid] += sred[tid + s];
        __syncthreads();
    }
    if (tid == 0) g_partial[b] = sred[0];
}

__global__ __launch_bounds__(512) void finalize_kernel(float* __restrict__ out) {
    __shared__ double s[BN];
    int t = threadIdx.x;
    s[t] = g_partial[t];
    __syncthreads();
    for (int st = 256; st; st >>= 1) {
        if (t < st) s[t] += s[t + st];
        __syncthreads();
    }
    if (t == 0) out[0] = (float)(s[0] / ((double)BN * KN * DN));
}

// ---------------------------------------------------------------------------
extern "C" void kernel_launch(void* const* d_in, const int* in_sizes, int n_in,
                              void* d_out, int out_size) {
    const float* X = (const float*)d_in[0];   // input
    const float* Y = (const float*)d_in[1];   // target
    float* out = (float*)d_out;

    cost_kernel<<<BN, 256>>>(X, Y);
    hungarian_kernel<<<BN, 32, KN * KN * (int)sizeof(__half)>>>();
    mse_kernel<<<BN, 256>>>(X, Y);
    finalize_kernel<<<1, 512>>>(out);
}

// round 7
// speedup vs baseline: 3.5249x; 1.1045x over previous
#include <cuda_runtime.h>
#include <cuda_fp16.h>
#include <cuda_bf16.h>
#include <cstdint>

#define BN 512   // batches
#define KN 128   // points per batch
#define DN 512   // feature dim

// Scratch (static device allocations allowed)
__device__ __half  g_cost[(size_t)BN * KN * KN];   // 16.8 MB, cost = -x.y (fp16)
__device__ int     g_perm[BN * KN];
__device__ double  g_partial[BN];

// ---------------------------------------------------------------------------
// helpers
// ---------------------------------------------------------------------------
__device__ __forceinline__ uint32_t smem_u32(const void* p) {
    return (uint32_t)__cvta_generic_to_shared(p);
}
__device__ __forceinline__ void ldsm_x4(uint32_t& r0, uint32_t& r1,
                                        uint32_t& r2, uint32_t& r3, uint32_t addr) {
    asm volatile("ldmatrix.sync.aligned.m8n8.x4.shared.b16 {%0,%1,%2,%3}, [%4];"
                 : "=r"(r0), "=r"(r1), "=r"(r2), "=r"(r3) : "r"(addr));
}
__device__ __forceinline__ void mma_bf16(float& c0, float& c1, float& c2, float& c3,
                                         uint32_t a0, uint32_t a1, uint32_t a2, uint32_t a3,
                                         uint32_t b0, uint32_t b1) {
    asm volatile("mma.sync.aligned.m16n8k16.row.col.f32.bf16.bf16.f32 "
                 "{%0,%1,%2,%3}, {%4,%5,%6,%7}, {%8,%9}, {%0,%1,%2,%3};"
                 : "+f"(c0), "+f"(c1), "+f"(c2), "+f"(c3)
                 : "r"(a0), "r"(a1), "r"(a2), "r"(a3), "r"(b0), "r"(b1));
}
__device__ __forceinline__ unsigned redux_min_u32(unsigned v) {
    unsigned r;
    asm("redux.sync.min.u32 %0, %1, 0xffffffff;" : "=r"(r) : "r"(v));
    return r;
}
__device__ __forceinline__ unsigned ordkey(float f) {
    unsigned u = __float_as_uint(f);
    return (u & 0x80000000u) ? ~u : (u | 0x80000000u);
}
__device__ __forceinline__ float unordkey(unsigned k) {
    unsigned u = (k & 0x80000000u) ? (k & 0x7fffffffu) : ~k;
    return __uint_as_float(u);
}

// ---------------------------------------------------------------------------
// Kernel 1: C[b][i][j] = -(X[b,i,:] . Y[b,j,:]), bf16 MMA, fp16 output.
// One CTA per batch. 256 thr = 8 warps in a 2(M) x 4(N) grid; warp tile 64x32.
// ---------------------------------------------------------------------------
__device__ __forceinline__ int chunk_off(int row, int c) {   // in 16B units
    return row * 8 + (c ^ (row & 7));
}

__global__ __launch_bounds__(256) void cost_kernel(const float* __restrict__ X,
                                                   const float* __restrict__ Y) {
    __shared__ uint4 Xs[1024];   // 16 KB: 128 rows x 8 chunks
    __shared__ uint4 Ys[1024];   // 16 KB

    const int b   = blockIdx.x;
    const int tid = threadIdx.x;
    const int w    = tid >> 5;
    const int lane = tid & 31;
    const int wm = w >> 2;       // 0..1  -> m base = wm*64
    const int wn = w & 3;        // 0..3  -> n base = wn*32

    const float* xb = X + (size_t)b * KN * DN;
    const float* yb = Y + (size_t)b * KN * DN;

    float acc[4][4][4];
#pragma unroll
    for (int mt = 0; mt < 4; mt++)
#pragma unroll
        for (int nt = 0; nt < 4; nt++)
#pragma unroll
            for (int q = 0; q < 4; q++) acc[mt][nt][q] = 0.f;

    const uint32_t xs_base = smem_u32(Xs);
    const uint32_t ys_base = smem_u32(Ys);

    for (int kb = 0; kb < 8; kb++) {     // K blocks of 64
#pragma unroll
        for (int qi = 0; qi < 4; qi++) {
            int q   = tid + 256 * qi;    // 0..1023
            int row = q >> 3;
            int c   = q & 7;
            const float* sx = xb + row * DN + kb * 64 + c * 8;
            const float* sy = yb + row * DN + kb * 64 + c * 8;
            float4 f0 = *(const float4*)sx;
            float4 f1 = *(const float4*)(sx + 4);
            uint4 pk;
            { __nv_bfloat162 t0 = __floats2bfloat162_rn(f0.x, f0.y); pk.x = *(uint32_t*)&t0; }
            { __nv_bfloat162 t1 = __floats2bfloat162_rn(f0.z, f0.w); pk.y = *(uint32_t*)&t1; }
            { __nv_bfloat162 t2 = __floats2bfloat162_rn(f1.x, f1.y); pk.z = *(uint32_t*)&t2; }
            { __nv_bfloat162 t3 = __floats2bfloat162_rn(f1.z, f1.w); pk.w = *(uint32_t*)&t3; }
            Xs[chunk_off(row, c)] = pk;
            float4 g0 = *(const float4*)sy;
            float4 g1 = *(const float4*)(sy + 4);
            { __nv_bfloat162 t0 = __floats2bfloat162_rn(g0.x, g0.y); pk.x = *(uint32_t*)&t0; }
            { __nv_bfloat162 t1 = __floats2bfloat162_rn(g0.z, g0.w); pk.y = *(uint32_t*)&t1; }
            { __nv_bfloat162 t2 = __floats2bfloat162_rn(g1.x, g1.y); pk.z = *(uint32_t*)&t2; }
            { __nv_bfloat162 t3 = __floats2bfloat162_rn(g1.z, g1.w); pk.w = *(uint32_t*)&t3; }
            Ys[chunk_off(row, c)] = pk;
        }
        __syncthreads();

#pragma unroll
        for (int ks = 0; ks < 4; ks++) {      // k16 steps within block
            const int sub = lane >> 3;
            const int r   = lane & 7;
            uint32_t A[4][4];
#pragma unroll
            for (int mt = 0; mt < 4; mt++) {
                int rowA = wm * 64 + mt * 16 + (sub & 1) * 8 + r;
                int kch  = ks * 2 + (sub >> 1);
                uint32_t ad = xs_base + (uint32_t)(chunk_off(rowA, kch) << 4);
                ldsm_x4(A[mt][0], A[mt][1], A[mt][2], A[mt][3], ad);
            }
            uint32_t Bf[2][4];
#pragma unroll
            for (int g2 = 0; g2 < 2; g2++) {
                int rowB = wn * 32 + g2 * 16 + (sub >> 1) * 8 + r;
                int kch  = ks * 2 + (sub & 1);
                uint32_t ad = ys_base + (uint32_t)(chunk_off(rowB, kch) << 4);
                ldsm_x4(Bf[g2][0], Bf[g2][1], Bf[g2][2], Bf[g2][3], ad);
            }
#pragma unroll
            for (int mt = 0; mt < 4; mt++)
#pragma unroll
                for (int nt = 0; nt < 4; nt++) {
                    int g2 = nt >> 1, h = nt & 1;
                    mma_bf16(acc[mt][nt][0], acc[mt][nt][1], acc[mt][nt][2], acc[mt][nt][3],
                             A[mt][0], A[mt][1], A[mt][2], A[mt][3],
                             Bf[g2][h * 2 + 0], Bf[g2][h * 2 + 1]);
                }
        }
        __syncthreads();
    }

    __half* cb = g_cost + (size_t)b * KN * KN;
    const int g = lane >> 2, t = lane & 3;
#pragma unroll
    for (int mt = 0; mt < 4; mt++)
#pragma unroll
        for (int nt = 0; nt < 4; nt++) {
            int row0 = wm * 64 + mt * 16 + g;
            int col  = wn * 32 + nt * 8 + 2 * t;
            *(__half2*)(cb + row0 * KN + col) =
                __floats2half2_rn(-acc[mt][nt][0], -acc[mt][nt][1]);
            *(__half2*)(cb + (row0 + 8) * KN + col) =
                __floats2half2_rn(-acc[mt][nt][2], -acc[mt][nt][3]);
        }
}

// ---------------------------------------------------------------------------
// Kernel 2: Jonker-Volgenant LAP with column-reduction init, one warp/batch.
// Lane owns 4 consecutive columns. v[j] = col min (dual feasible with u=0);
// each column greedily matched to its argmin row (first col wins via
// atomicMin). Only leftover free rows run the Dijkstra SAP phase.
// ---------------------------------------------------------------------------
__global__ __launch_bounds__(32) void hungarian_kernel() {
    extern __shared__ __half a_s[];        // 128*128 halfs = 32 KB
    __shared__ int2 pu_s[KN + 1];          // [col] = {row (1-based, 0=free), u_bits}
    __shared__ int  claim_s[KN + 1];       // [row] = claiming column (1-based)
    __shared__ int  freerows_s[KN];

    const int b = blockIdx.x;
    const int lane = threadIdx.x;
    const float INF = 1e30f;
    const int SENT = 0x7fffffff;

    {   // load cost tile (2048 uint4)
        const uint4* src = (const uint4*)(g_cost + (size_t)b * KN * KN);
        uint4* dst = (uint4*)a_s;
#pragma unroll
        for (int q = 0; q < 64; q++) dst[lane + 32 * q] = src[lane + 32 * q];
    }
    for (int t = lane; t <= KN; t += 32) claim_s[t] = SENT;
    __syncwarp();

    // ---- column reduction: v[j] = min_i a[i][j], argmin row per column ----
    float v_r[4] = {INF, INF, INF, INF};
    int   argr[4] = {1, 1, 1, 1};
    for (int r = 0; r < KN; r++) {
        uint2 rw = *(const uint2*)(a_s + r * KN + 4 * lane);
        float2 f01 = __half22float2(*(const __half2*)&rw.x);
        float2 f23 = __half22float2(*(const __half2*)&rw.y);
        float av[4] = { f01.x, f01.y, f23.x, f23.y };
#pragma unroll
        for (int c = 0; c < 4; c++)
            if (av[c] < v_r[c]) { v_r[c] = av[c]; argr[c] = r + 1; }
    }
    // greedy claim: lowest column index wins a contested row
#pragma unroll
    for (int c = 0; c < 4; c++)
        atomicMin(&claim_s[argr[c]], 4 * lane + c + 1);
    __syncwarp();
#pragma unroll
    for (int c = 0; c < 4; c++) {
        int j = 4 * lane + c + 1;
        pu_s[j] = (claim_s[argr[c]] == j) ? make_int2(argr[c], 0)
                                          : make_int2(0, 0);
    }
    __syncwarp();

    // ---- build free-row list (rows not claimed by any column) ----
    int nfree = 0;
#pragma unroll
    for (int g = 0; g < 4; g++) {
        int row = g * 32 + lane + 1;
        bool fr = (claim_s[row] == SENT);
        unsigned m = __ballot_sync(0xffffffffu, fr);
        int pos = __popc(m & ((1u << lane) - 1));
        if (fr) freerows_s[nfree + pos] = row;
        nfree += __popc(m);
    }
    __syncwarp();

    // ---- SAP phase for free rows ----
    for (int t = 0; t < nfree; t++) {
        const int irow = freerows_s[t];
        float dist[4] = {INF, INF, INF, INF};
        int   way[4]  = {0, 0, 0, 0};
        bool  used[4] = {false, false, false, false};
        int   i0 = irow;
        float u_i0 = 0.f;
        float D  = 0.f;
        int   prevj = 0;
        int   j0;

        for (;;) {
            const float s = D - u_i0;
            uint2 rw = *(const uint2*)(a_s + (i0 - 1) * KN + 4 * lane);
            float2 f01 = __half22float2(*(const __half2*)&rw.x);
            float2 f23 = __half22float2(*(const __half2*)&rw.y);
            float av[4] = { f01.x, f01.y, f23.x, f23.y };

            unsigned bestkey = 0xffffffffu;
#pragma unroll
            for (int c = 0; c < 4; c++) {
                if (!used[c]) {
                    float cur = av[c] + (s - v_r[c]);
                    if (cur < dist[c]) { dist[c] = cur; way[c] = prevj; }
                    unsigned k = (ordkey(dist[c]) & ~127u) | (unsigned)(4 * lane + c);
                    bestkey = min(bestkey, k);
                }
            }
            unsigned mk = redux_min_u32(bestkey);
            D = unordkey(mk);                 // uniform across lanes
            int jg = mk & 127;                // winning column, 0-based
            int j1 = jg + 1;
            prevj = j1;

            int2 pu = pu_s[j1];               // {row, u}, one LDS.64
            bool done = (pu.x == 0);
            if (!done && (jg >> 2) == lane) used[jg & 3] = true;
            if (done) { j0 = j1; break; }
            i0 = pu.x;
            u_i0 = __int_as_float(pu.y);
        }

        // deferred dual updates (old matching; each matched row in exactly 1 col)
#pragma unroll
        for (int c = 0; c < 4; c++) {
            if (used[c]) {
                float dd = D - dist[c];
                v_r[c] -= dd;
                int j = 4 * lane + c + 1;
                pu_s[j].y = __float_as_int(__int_as_float(pu_s[j].y) + dd);
            }
        }
        if (lane == 0) pu_s[0] = make_int2(irow, __float_as_int(D));
        __syncwarp();

        // augment: shift {row,u} pairs along alternating path
        int jj = j0;
        while (jj != 0) {
            int o = jj - 1;
            int c = o & 3;
            int sel = (c == 0) ? way[0] : (c == 1) ? way[1] : (c == 2) ? way[2] : way[3];
            int jn = __shfl_sync(0xffffffffu, sel, o >> 2);
            if (lane == 0) pu_s[jj] = pu_s[jn];
            __syncwarp();
            jj = jn;
        }
        __syncwarp();
    }

    // emit row->col permutation: perm[row-1] = col-1
#pragma unroll
    for (int c = 0; c < 4; c++) {
        int j = 4 * lane + c + 1;
        g_perm[b * KN + pu_s[j].x - 1] = j - 1;
    }
}

// ---------------------------------------------------------------------------
// Kernel 3: per-batch sum of (x - y[perm])^2 in fp32, deterministic reduction
// ---------------------------------------------------------------------------
__global__ __launch_bounds__(256) void mse_kernel(const float* __restrict__ X,
                                                  const float* __restrict__ Y) {
    int b = blockIdx.x, tid = threadIdx.x;
    __shared__ int sperm[KN];
    if (tid < KN) sperm[tid] = g_perm[b * KN + tid];
    __syncthreads();

    const float4* xb = (const float4*)(X + (size_t)b * KN * DN);
    const float4* yb = (const float4*)(Y + (size_t)b * KN * DN);
    const int F4_PER_ROW = DN / 4;   // 128
    float acc = 0.f;
    for (int idx = tid; idx < KN * F4_PER_ROW; idx += 256) {
        int row = idx >> 7, col = idx & (F4_PER_ROW - 1);
        float4 xv = xb[row * F4_PER_ROW + col];
        float4 yv = yb[sperm[row] * F4_PER_ROW + col];
        float d0 = xv.x - yv.x, d1 = xv.y - yv.y;
        float d2 = xv.z - yv.z, d3 = xv.w - yv.w;
        acc += d0 * d0 + d1 * d1 + d2 * d2 + d3 * d3;
    }
    __shared__ double sred[256];
    sred[tid] = (double)acc;
    __syncthreads();
    for (int s = 128; s; s >>= 1) {
        if (tid < s) sred[tid] += sred[tid + s];
        __syncthreads();
    }
    if (tid == 0) g_partial[b] = sred[0];
}

__global__ __launch_bounds__(512) void finalize_kernel(float* __restrict__ out) {
    __shared__ double s[BN];
    int t = threadIdx.x;
    s[t] = g_partial[t];
    __syncthreads();
    for (int st = 256; st; st >>= 1) {
        if (t < st) s[t] += s[t + st];
        __syncthreads();
    }
    if (t == 0) out[0] = (float)(s[0] / ((double)BN * KN * DN));
}

// ---------------------------------------------------------------------------
extern "C" void kernel_launch(void* const* d_in, const int* in_sizes, int n_in,
                              void* d_out, int out_size) {
    const float* X = (const float*)d_in[0];   // input
    const float* Y = (const float*)d_in[1];   // target
    float* out = (float*)d_out;

    cost_kernel<<<BN, 256>>>(X, Y);
    hungarian_kernel<<<BN, 32, KN * KN * (int)sizeof(__half)>>>();
    mse_kernel<<<BN, 256>>>(X, Y);
    finalize_kernel<<<1, 512>>>(out);
}